// round 6
// baseline (speedup 1.0000x reference)
#include <cuda_runtime.h>
#include <cuda_bf16.h>
#include <math.h>
#include <stdint.h>

#define NB     4096
#define NROWS  8192
#define DDIM   128
#define NTILE  64          // 8192 / 128
#define NCTA   2080        // NTILE*(NTILE+1)/2 upper-triangle tiles
#define E2LOG2 2.885390081777927f   // 2 * log2(e)

// ---------------- static scratch (no allocations allowed) ----------------
__device__ __nv_bfloat16 g_hi[NROWS * DDIM];
__device__ float         g_rowsum[NROWS];
__device__ float         g_pos[NROWS];
__device__ float         g_self[NROWS];

// ---------------- helpers ----------------
__device__ __forceinline__ uint32_t smem_u32(const void* p) {
    uint32_t a;
    asm("{ .reg .u64 t; cvta.to.shared.u64 t, %1; cvt.u32.u64 %0, t; }"
        : "=r"(a) : "l"(p));
    return a;
}
__device__ __forceinline__ void ldsm4(uint32_t* r, uint32_t addr) {
    asm volatile("ldmatrix.sync.aligned.m8n8.x4.shared.b16 {%0,%1,%2,%3}, [%4];"
                 : "=r"(r[0]), "=r"(r[1]), "=r"(r[2]), "=r"(r[3]) : "r"(addr));
}
__device__ __forceinline__ void mma16816(float* d, const uint32_t* a,
                                         uint32_t b0, uint32_t b1) {
    asm volatile("mma.sync.aligned.m16n8k16.row.col.f32.bf16.bf16.f32 "
                 "{%0,%1,%2,%3}, {%4,%5,%6,%7}, {%8,%9}, {%0,%1,%2,%3};"
                 : "+f"(d[0]), "+f"(d[1]), "+f"(d[2]), "+f"(d[3])
                 : "r"(a[0]), "r"(a[1]), "r"(a[2]), "r"(a[3]), "r"(b0), "r"(b1));
}

// smem tile layout: 128 rows, pitch 272 B (17x16B -> conflict-free ldmatrix)
#define PITCH    272
#define SM_A     0
#define SM_B     (128 * PITCH)
#define SM_ROWS  (2 * 128 * PITCH)
#define SM_COLS  (SM_ROWS + 128 * 4)
#define SMEM_SZ  (SM_COLS + 128 * 4)

// ---------------- K1: normalize pair + bf16 + positives/self ----------------
__global__ void __launch_bounds__(256) k_norm(const float* __restrict__ p1,
                                              const float* __restrict__ p2) {
    int gw = (blockIdx.x * blockDim.x + threadIdx.x) >> 5;   // pair index 0..NB-1
    int lane = threadIdx.x & 31;
    if (gw >= NB) return;
    float4 v1 = *(const float4*)(p1 + (size_t)gw * DDIM + lane * 4);
    float4 v2 = *(const float4*)(p2 + (size_t)gw * DDIM + lane * 4);
    float ss1 = v1.x * v1.x + v1.y * v1.y + v1.z * v1.z + v1.w * v1.w;
    float ss2 = v2.x * v2.x + v2.y * v2.y + v2.z * v2.z + v2.w * v2.w;
    float cx  = v1.x * v2.x + v1.y * v2.y + v1.z * v2.z + v1.w * v2.w;
#pragma unroll
    for (int o = 16; o; o >>= 1) {
        ss1 += __shfl_xor_sync(0xffffffffu, ss1, o);
        ss2 += __shfl_xor_sync(0xffffffffu, ss2, o);
        cx  += __shfl_xor_sync(0xffffffffu, cx,  o);
    }
    float inv1 = 1.0f / fmaxf(sqrtf(ss1), 1e-12f);
    float inv2 = 1.0f / fmaxf(sqrtf(ss2), 1e-12f);

#pragma unroll
    for (int half = 0; half < 2; ++half) {
        float4 v = half ? v2 : v1;
        float inv = half ? inv2 : inv1;
        size_t base = (size_t)(half ? gw + NB : gw) * DDIM + lane * 4;
        v.x *= inv; v.y *= inv; v.z *= inv; v.w *= inv;
        __nv_bfloat162 h01; h01.x = __float2bfloat16(v.x); h01.y = __float2bfloat16(v.y);
        __nv_bfloat162 h23; h23.x = __float2bfloat16(v.z); h23.y = __float2bfloat16(v.w);
        *(__nv_bfloat162*)(g_hi + base)     = h01;
        *(__nv_bfloat162*)(g_hi + base + 2) = h23;
    }
    if (lane == 0) {
        float pos = cx * inv1 * inv2;
        g_pos[gw] = pos;            g_pos[gw + NB] = pos;
        g_self[gw] = ss1 * inv1 * inv1;
        g_self[gw + NB] = ss2 * inv2 * inv2;
        g_rowsum[gw] = 0.0f;        g_rowsum[gw + NB] = 0.0f;
    }
}

// ---------------- K2: HMMA sim-GEMM (upper triangle), 4 warps of 64x64 ----------------
extern __shared__ char smem_raw[];

__global__ void __launch_bounds__(128, 2) k_gemm() {
    const int tid  = threadIdx.x;
    const int wid  = tid >> 5;
    const int lane = tid & 31;

    // decode upper-triangle tile (bi <= bj) from linear blockIdx
    int t = blockIdx.x;
    int bi = (int)(64.5f - sqrtf(64.5f * 64.5f - 2.0f * (float)t));
    while (bi * NTILE - (bi * (bi - 1)) / 2 > t) --bi;
    while ((bi + 1) * NTILE - ((bi + 1) * bi) / 2 <= t) ++bi;
    const int bj = bi + (t - (bi * NTILE - (bi * (bi - 1)) / 2));
    const bool diag = (bi == bj);
    const int r0 = bi * 128;
    const int c0 = bj * 128;

    float* smrows = (float*)(smem_raw + SM_ROWS);
    float* smcols = (float*)(smem_raw + SM_COLS);
    smrows[tid] = 0.0f; smcols[tid] = 0.0f;

    // load A (rows r0..+127) and B (rows c0..+127)
#pragma unroll
    for (int it = 0; it < 16; ++it) {
        int idx = tid + it * 128;
        int row = idx >> 4;
        int seg = idx & 15;
        uint32_t so = (uint32_t)(row * PITCH + seg * 16);
        *(uint4*)(smem_raw + SM_A + so) =
            *(const uint4*)(g_hi + (size_t)(r0 + row) * DDIM + seg * 8);
        *(uint4*)(smem_raw + SM_B + so) =
            *(const uint4*)(g_hi + (size_t)(c0 + row) * DDIM + seg * 8);
    }
    __syncthreads();

    const uint32_t sb = smem_u32(smem_raw);
    const int wm = wid >> 1;          // 0..1 -> rows 64*wm
    const int wn = wid & 1;           // 0..1 -> cols 64*wn

    const uint32_t a_base = sb +
        (uint32_t)((64 * wm + (lane & 15)) * PITCH + (lane >> 4) * 16);
    const int brow = 64 * wn + (lane & 7) + ((lane >> 4) << 3);
    const uint32_t b_base = sb + SM_B +
        (uint32_t)(brow * PITCH + ((lane >> 3) & 1) * 16);

    float acc[4][8][4];
#pragma unroll
    for (int mi = 0; mi < 4; ++mi)
#pragma unroll
        for (int nj = 0; nj < 8; ++nj)
#pragma unroll
            for (int e = 0; e < 4; ++e) acc[mi][nj][e] = 0.0f;

#pragma unroll
    for (int kk = 0; kk < 8; ++kk) {
        uint32_t b[4][4];
#pragma unroll
        for (int nq = 0; nq < 4; ++nq)
            ldsm4(b[nq], b_base + nq * 16 * PITCH + kk * 32);
#pragma unroll
        for (int mi = 0; mi < 4; ++mi) {
            uint32_t a[4];
            ldsm4(a, a_base + kk * 32 + mi * 16 * PITCH);
#pragma unroll
            for (int nq = 0; nq < 4; ++nq) {
                mma16816(acc[mi][2 * nq],     a, b[nq][0], b[nq][1]);
                mma16816(acc[mi][2 * nq + 1], a, b[nq][2], b[nq][3]);
            }
        }
    }

    // exp(2*sim) = exp2(E2LOG2 * sim), in place
#pragma unroll
    for (int mi = 0; mi < 4; ++mi)
#pragma unroll
        for (int nj = 0; nj < 8; ++nj)
#pragma unroll
            for (int e = 0; e < 4; ++e)
                acc[mi][nj][e] = exp2f(E2LOG2 * acc[mi][nj][e]);

    // row partial sums: quad shfl-reduce, then 1 atomic per row per quad
    const int rbase = 64 * wm + (lane >> 2);
#pragma unroll
    for (int mi = 0; mi < 4; ++mi) {
        float slo = 0.0f, shi = 0.0f;
#pragma unroll
        for (int nj = 0; nj < 8; ++nj) {
            slo += acc[mi][nj][0] + acc[mi][nj][1];
            shi += acc[mi][nj][2] + acc[mi][nj][3];
        }
        slo += __shfl_xor_sync(0xffffffffu, slo, 1);
        slo += __shfl_xor_sync(0xffffffffu, slo, 2);
        shi += __shfl_xor_sync(0xffffffffu, shi, 1);
        shi += __shfl_xor_sync(0xffffffffu, shi, 2);
        if ((lane & 3) == 0) {
            atomicAdd(&smrows[rbase + 16 * mi],     slo);
            atomicAdd(&smrows[rbase + 16 * mi + 8], shi);
        }
    }

    // column partial sums (off-diagonal tiles credit the transpose rows)
    if (!diag) {
#pragma unroll
        for (int nj = 0; nj < 8; ++nj) {
#pragma unroll
            for (int c2 = 0; c2 < 2; ++c2) {
                float v = 0.0f;
#pragma unroll
                for (int mi = 0; mi < 4; ++mi)
                    v += acc[mi][nj][c2] + acc[mi][nj][c2 + 2];
                v += __shfl_down_sync(0xffffffffu, v, 16);
                v += __shfl_down_sync(0xffffffffu, v, 8);
                v += __shfl_down_sync(0xffffffffu, v, 4);
                if (lane < 4)
                    atomicAdd(&smcols[64 * wn + 8 * nj + lane * 2 + c2], v);
            }
        }
    }
    __syncthreads();
    atomicAdd(&g_rowsum[r0 + tid], smrows[tid]);
    if (!diag) atomicAdd(&g_rowsum[c0 + tid], smcols[tid]);
}

// ---------------- K3: final reduction ----------------
__global__ void __launch_bounds__(1024) k_final(float* __restrict__ out) {
    __shared__ float red[1024];
    int tid = threadIdx.x;
    float local = 0.0f;
#pragma unroll
    for (int r = tid; r < NROWS; r += 1024) {
        float den = g_rowsum[r] - exp2f(E2LOG2 * g_self[r]);
        local += __logf(den) - 2.0f * g_pos[r];
    }
    red[tid] = local;
    __syncthreads();
#pragma unroll
    for (int o = 512; o; o >>= 1) {
        if (tid < o) red[tid] += red[tid + o];
        __syncthreads();
    }
    if (tid == 0) out[0] = red[0] / (float)NROWS;
}

// ---------------- launcher ----------------
extern "C" void kernel_launch(void* const* d_in, const int* in_sizes, int n_in,
                              void* d_out, int out_size) {
    const float* p1 = (const float*)d_in[0];
    const float* p2 = (const float*)d_in[1];
    float* out = (float*)d_out;

    cudaFuncSetAttribute(k_gemm, cudaFuncAttributeMaxDynamicSharedMemorySize, SMEM_SZ);

    k_norm<<<NB / 8, 256>>>(p1, p2);
    k_gemm<<<NCTA, 128, SMEM_SZ>>>();
    k_final<<<1, 1024>>>(out);
}